// round 1
// baseline (speedup 1.0000x reference)
#include <cuda_runtime.h>
#include <cuda_bf16.h>
#include <math.h>

// Problem constants
#define BB 512   // batch
#define DD 512   // input dim / columns
#define LL 32    // latent
#define HH 300   // hidden
#define BT 64    // batch tile in decoder
#define KC 32    // k-chunk in decoder phase 3

// ---------------------------------------------------------------------------
// Scratch (device globals: allocation-free rule)
// ---------------------------------------------------------------------------
__device__ float g_h1[BB * HH];
__device__ float g_h2[BB * HH];
__device__ float g_z[BB * LL];

// ---------------------------------------------------------------------------
// Generic tiled SGEMM with bias + relu epilogue: C = relu(A[M,K] @ Bw[K,N] + b)
// block 256 threads, 64x64 tile, 4x4 micro-tile, BK=8
// ---------------------------------------------------------------------------
__global__ void gemm_bias_relu(const float* __restrict__ A,
                               const float* __restrict__ Bw,
                               const float* __restrict__ bias,
                               float* __restrict__ C,
                               int M, int N, int K) {
    const int BK = 8;
    __shared__ float As[BK][64];
    __shared__ float Bs[BK][64];
    int tid = threadIdx.x;
    int tx = tid % 16, ty = tid / 16;
    int rowBase = blockIdx.y * 64;
    int colBase = blockIdx.x * 64;
    float acc[4][4] = {};
    for (int k0 = 0; k0 < K; k0 += BK) {
        #pragma unroll
        for (int i = 0; i < 2; i++) {
            int idx = tid * 2 + i;          // 0..511
            int r = idx / BK, kk = idx % BK;
            int gr = rowBase + r, gk = k0 + kk;
            As[kk][r] = (gr < M && gk < K) ? A[gr * K + gk] : 0.f;
        }
        #pragma unroll
        for (int i = 0; i < 2; i++) {
            int idx = tid * 2 + i;
            int kk = idx / 64, c = idx % 64;
            int gc = colBase + c, gk = k0 + kk;
            Bs[kk][c] = (gc < N && gk < K) ? Bw[gk * N + gc] : 0.f;
        }
        __syncthreads();
        #pragma unroll
        for (int kk = 0; kk < BK; kk++) {
            float a[4], b[4];
            #pragma unroll
            for (int i = 0; i < 4; i++) a[i] = As[kk][ty * 4 + i];
            #pragma unroll
            for (int jj = 0; jj < 4; jj++) b[jj] = Bs[kk][tx * 4 + jj];
            #pragma unroll
            for (int i = 0; i < 4; i++)
                #pragma unroll
                for (int jj = 0; jj < 4; jj++)
                    acc[i][jj] += a[i] * b[jj];
        }
        __syncthreads();
    }
    #pragma unroll
    for (int i = 0; i < 4; i++) {
        int r = rowBase + ty * 4 + i;
        if (r >= M) continue;
        #pragma unroll
        for (int jj = 0; jj < 4; jj++) {
            int c = colBase + tx * 4 + jj;
            if (c >= N) continue;
            float v = acc[i][jj] + bias[c];
            C[r * N + c] = v > 0.f ? v : 0.f;
        }
    }
}

// ---------------------------------------------------------------------------
// Heads: z_mean, z_log_var, z from h2. One thread per (b, l).
// ---------------------------------------------------------------------------
__global__ void heads_kernel(const float* __restrict__ zm_w,
                             const float* __restrict__ zm_b,
                             const float* __restrict__ zl_w,
                             const float* __restrict__ zl_b,
                             const float* __restrict__ eps,
                             float* __restrict__ z_out,
                             float* __restrict__ zm_out,
                             float* __restrict__ zl_out) {
    int tid = blockIdx.x * blockDim.x + threadIdx.x;
    if (tid >= BB * LL) return;
    int b = tid >> 5, l = tid & 31;
    const float* h2row = g_h2 + b * HH;
    float am = 0.f, al = 0.f;
    for (int h = 0; h < HH; h++) {
        float hv = __ldg(h2row + h);
        am += hv * zm_w[h * LL + l];
        al += hv * zl_w[h * LL + l];
    }
    am += zm_b[l];
    al += zl_b[l];
    float zv = am + eps[tid] * expf(0.5f * al);
    zm_out[tid] = am;
    zl_out[tid] = al;
    z_out[tid] = zv;
    g_z[tid] = zv;
}

// ---------------------------------------------------------------------------
// Fused decoder: one CTA per (column j, 64-row batch tile).
//   masked = W[j]*z  ->  g1 = relu(masked @ gen_w1)  (kept in SMEM, transposed)
//   x_rec[b] = sum_k relu(g1[b,:] @ gen_w2[:,k] + b2[k]) * col_w[j,k] + col_b[j]
// Dynamic smem layout (floats):
//   zsm  [64][33]          = 2112
//   g1t  [300][64]         = 19200
//   wbuf                   = 9600  (gen_w1 in phase2, gen_w2 k-chunks in phase3)
//   outs [64]
// ---------------------------------------------------------------------------
__global__ void __launch_bounds__(256, 1)
decoder_kernel(const float* __restrict__ Wmask,
               const float* __restrict__ gen_w1,
               const float* __restrict__ gen_w2,
               const float* __restrict__ gen_b2,
               const float* __restrict__ col_w,
               const float* __restrict__ col_b,
               float* __restrict__ xmean) {
    extern __shared__ float sm[];
    float* zsm  = sm;                       // [64][33]
    float* g1t  = sm + 64 * 33;             // [300][64]
    float* wbuf = g1t + HH * BT;            // 9600 floats
    float* outs = wbuf + 9600;              // [64]
    __shared__ float wjs[LL];

    const int tid = threadIdx.x;
    const int j = blockIdx.y;
    const int b0 = blockIdx.x * BT;

    if (tid < LL) wjs[tid] = Wmask[j * LL + tid];
    if (tid < BT) outs[tid] = 0.f;
    __syncthreads();

    // Stage masked z tile and gen_w1
    for (int idx = tid; idx < BT * LL; idx += 256) {
        int bl = idx >> 5, l = idx & 31;
        zsm[bl * 33 + l] = g_z[(b0 + bl) * LL + l] * wjs[l];
    }
    for (int idx = tid; idx < LL * HH; idx += 256) {
        wbuf[idx] = gen_w1[idx];            // [l][h]
    }
    __syncthreads();

    // Phase 2: g1t[h][bl] = relu(sum_l zsm[bl][l] * gen_w1[l][h])
    {
        int tx = tid & 31;
        int ty = tid >> 5;
        int bl = tx + ((ty & 1) << 5);      // 0..63
        int h0 = ty >> 1;                   // 0..3
        float zr[LL];
        #pragma unroll
        for (int l = 0; l < LL; l++) zr[l] = zsm[bl * 33 + l];
        for (int h = h0; h < HH; h += 4) {
            float a = 0.f;
            #pragma unroll
            for (int l = 0; l < LL; l++) a += zr[l] * wbuf[l * HH + h];
            g1t[h * BT + bl] = fmaxf(a, 0.f);
        }
    }

    // Phase 3: g2 + relu + col_w reduce, k in chunks of 32
    const int tx = tid & 31, ty = tid >> 5;
    const int q  = tx & 15;                 // bl quarter (4 consecutive rows)
    const int kh = tx >> 4;                 // 0/1
    const int blb = q * 4;
    const int k0  = 2 * (ty + 8 * kh);      // 0,2,...,30 (pair of k's)
    float psum0 = 0.f, psum1 = 0.f, psum2 = 0.f, psum3 = 0.f;

    for (int koff = 0; koff < HH; koff += KC) {
        __syncthreads();                    // wbuf reuse barrier
        for (int idx = tid; idx < HH * KC; idx += 256) {
            int h = idx >> 5, kk = idx & 31;
            int kg = koff + kk;
            wbuf[idx] = (kg < HH) ? gen_w2[h * HH + kg] : 0.f;
        }
        __syncthreads();

        float acc00 = 0.f, acc10 = 0.f, acc20 = 0.f, acc30 = 0.f;
        float acc01 = 0.f, acc11 = 0.f, acc21 = 0.f, acc31 = 0.f;
        #pragma unroll 4
        for (int h = 0; h < HH; h++) {
            float4 g = *reinterpret_cast<const float4*>(&g1t[h * BT + blb]);
            float2 w = *reinterpret_cast<const float2*>(&wbuf[h * KC + k0]);
            acc00 += g.x * w.x; acc10 += g.y * w.x;
            acc20 += g.z * w.x; acc30 += g.w * w.x;
            acc01 += g.x * w.y; acc11 += g.y * w.y;
            acc21 += g.z * w.y; acc31 += g.w * w.y;
        }
        #pragma unroll
        for (int kk = 0; kk < 2; kk++) {
            int kg = koff + k0 + kk;
            if (kg < HH) {
                float bb = gen_b2[kg];
                float cw = col_w[j * HH + kg];
                float a0 = kk ? acc01 : acc00;
                float a1 = kk ? acc11 : acc10;
                float a2 = kk ? acc21 : acc20;
                float a3 = kk ? acc31 : acc30;
                psum0 += fmaxf(a0 + bb, 0.f) * cw;
                psum1 += fmaxf(a1 + bb, 0.f) * cw;
                psum2 += fmaxf(a2 + bb, 0.f) * cw;
                psum3 += fmaxf(a3 + bb, 0.f) * cw;
            }
        }
    }

    atomicAdd(&outs[blb + 0], psum0);
    atomicAdd(&outs[blb + 1], psum1);
    atomicAdd(&outs[blb + 2], psum2);
    atomicAdd(&outs[blb + 3], psum3);
    __syncthreads();
    if (tid < BT) {
        xmean[(b0 + tid) * DD + j] = outs[tid] + col_b[j];
    }
}

// ---------------------------------------------------------------------------
// Launch
// ---------------------------------------------------------------------------
extern "C" void kernel_launch(void* const* d_in, const int* in_sizes, int n_in,
                              void* d_out, int out_size) {
    const float* x      = (const float*)d_in[0];
    const float* eps    = (const float*)d_in[1];
    const float* Wmask  = (const float*)d_in[2];
    const float* qz_w1  = (const float*)d_in[3];
    const float* qz_b1  = (const float*)d_in[4];
    const float* qz_w2  = (const float*)d_in[5];
    const float* qz_b2  = (const float*)d_in[6];
    const float* zm_w   = (const float*)d_in[7];
    const float* zm_b   = (const float*)d_in[8];
    const float* zl_w   = (const float*)d_in[9];
    const float* zl_b   = (const float*)d_in[10];
    const float* gen_w1 = (const float*)d_in[11];
    const float* gen_w2 = (const float*)d_in[12];
    const float* gen_b2 = (const float*)d_in[13];
    const float* col_w  = (const float*)d_in[14];
    const float* col_b  = (const float*)d_in[15];

    float* out    = (float*)d_out;
    float* xmean  = out;                       // [B, D]
    float* z_out  = out + BB * DD;             // [B, L]
    float* zm_out = z_out + BB * LL;
    float* zl_out = zm_out + BB * LL;

    float *h1_ptr = nullptr, *h2_ptr = nullptr;
    cudaGetSymbolAddress((void**)&h1_ptr, g_h1);
    cudaGetSymbolAddress((void**)&h2_ptr, g_h2);

    // Encoder GEMM 1: h1 = relu(x @ qz_w1 + qz_b1)   [512,300] K=512
    {
        dim3 grid((HH + 63) / 64, (BB + 63) / 64);
        gemm_bias_relu<<<grid, 256>>>(x, qz_w1, qz_b1, h1_ptr, BB, HH, DD);
    }
    // Encoder GEMM 2: h2 = relu(h1 @ qz_w2 + qz_b2)  [512,300] K=300
    {
        dim3 grid((HH + 63) / 64, (BB + 63) / 64);
        gemm_bias_relu<<<grid, 256>>>(h1_ptr, qz_w2, qz_b2, h2_ptr, BB, HH, HH);
    }
    // Heads: z_mean, z_log_var, z
    heads_kernel<<<(BB * LL + 255) / 256, 256>>>(zm_w, zm_b, zl_w, zl_b, eps,
                                                 z_out, zm_out, zl_out);
    // Fused decoder
    {
        const int smem_bytes = (64 * 33 + HH * BT + 9600 + 64) * sizeof(float);
        cudaFuncSetAttribute(decoder_kernel,
                             cudaFuncAttributeMaxDynamicSharedMemorySize,
                             smem_bytes);
        dim3 grid(BB / BT, DD);
        decoder_kernel<<<grid, 256, smem_bytes>>>(Wmask, gen_w1, gen_w2, gen_b2,
                                                  col_w, col_b, xmean);
    }
}

// round 2
// speedup vs baseline: 3.3607x; 3.3607x over previous
#include <cuda_runtime.h>
#include <cuda_bf16.h>
#include <math.h>
#include <stdint.h>

// Problem constants
#define BB 512   // batch
#define DD 512   // input dim / columns
#define LL 32    // latent
#define HH 300   // hidden
#define MT 64    // batch tile (M) in decoder
#define NPAD 304 // padded N (38 * 8)
#define NTW 19   // n-tiles per warp (two n-half warps cover 38)
#define KT2 38   // k-tiles in gemm2 (304/8)
#define G1S 308  // G1 smem stride (mod 32 == 20 -> conflict-free A frags)
#define WS  312  // W1/W2 smem stride (mod 32 == 24 -> conflict-free B frags)
#define ZS  36   // Zms stride (mod 32 == 4 -> conflict-free A frags)

// ---------------------------------------------------------------------------
// Scratch (device globals: allocation-free rule)
// ---------------------------------------------------------------------------
__device__ float g_h1[BB * HH];
__device__ float g_h2[BB * HH];
__device__ float g_z[BB * LL];

// ---------------------------------------------------------------------------
// TF32 helpers
// ---------------------------------------------------------------------------
__device__ __forceinline__ uint32_t f2tf(float f) {
    uint32_t u;
    asm("cvt.rna.tf32.f32 %0, %1;" : "=r"(u) : "f"(f));
    return u;
}

__device__ __forceinline__ void mma8(float* d, const uint32_t* a, const uint32_t* b) {
    asm volatile(
        "mma.sync.aligned.m16n8k8.row.col.f32.tf32.tf32.f32 "
        "{%0,%1,%2,%3}, {%4,%5,%6,%7}, {%8,%9}, {%0,%1,%2,%3};\n"
        : "+f"(d[0]), "+f"(d[1]), "+f"(d[2]), "+f"(d[3])
        : "r"(a[0]), "r"(a[1]), "r"(a[2]), "r"(a[3]), "r"(b[0]), "r"(b[1]));
}

// ---------------------------------------------------------------------------
// Generic tiled SGEMM with bias + relu: C = relu(A[M,K] @ Bw[K,N] + b)
// ---------------------------------------------------------------------------
__global__ void gemm_bias_relu(const float* __restrict__ A,
                               const float* __restrict__ Bw,
                               const float* __restrict__ bias,
                               float* __restrict__ C,
                               int M, int N, int K) {
    const int BK = 8;
    __shared__ float As[BK][64];
    __shared__ float Bs[BK][64];
    int tid = threadIdx.x;
    int tx = tid % 16, ty = tid / 16;
    int rowBase = blockIdx.y * 64;
    int colBase = blockIdx.x * 64;
    float acc[4][4] = {};
    for (int k0 = 0; k0 < K; k0 += BK) {
        #pragma unroll
        for (int i = 0; i < 2; i++) {
            int idx = tid * 2 + i;
            int r = idx / BK, kk = idx % BK;
            int gr = rowBase + r, gk = k0 + kk;
            As[kk][r] = (gr < M && gk < K) ? A[gr * K + gk] : 0.f;
        }
        #pragma unroll
        for (int i = 0; i < 2; i++) {
            int idx = tid * 2 + i;
            int kk = idx / 64, c = idx % 64;
            int gc = colBase + c, gk = k0 + kk;
            Bs[kk][c] = (gc < N && gk < K) ? Bw[gk * N + gc] : 0.f;
        }
        __syncthreads();
        #pragma unroll
        for (int kk = 0; kk < BK; kk++) {
            float a[4], b[4];
            #pragma unroll
            for (int i = 0; i < 4; i++) a[i] = As[kk][ty * 4 + i];
            #pragma unroll
            for (int jj = 0; jj < 4; jj++) b[jj] = Bs[kk][tx * 4 + jj];
            #pragma unroll
            for (int i = 0; i < 4; i++)
                #pragma unroll
                for (int jj = 0; jj < 4; jj++)
                    acc[i][jj] += a[i] * b[jj];
        }
        __syncthreads();
    }
    #pragma unroll
    for (int i = 0; i < 4; i++) {
        int r = rowBase + ty * 4 + i;
        if (r >= M) continue;
        #pragma unroll
        for (int jj = 0; jj < 4; jj++) {
            int c = colBase + tx * 4 + jj;
            if (c >= N) continue;
            float v = acc[i][jj] + bias[c];
            C[r * N + c] = v > 0.f ? v : 0.f;
        }
    }
}

// ---------------------------------------------------------------------------
// Heads: z_mean, z_log_var, z from h2. One thread per (b, l).
// ---------------------------------------------------------------------------
__global__ void heads_kernel(const float* __restrict__ zm_w,
                             const float* __restrict__ zm_b,
                             const float* __restrict__ zl_w,
                             const float* __restrict__ zl_b,
                             const float* __restrict__ eps,
                             float* __restrict__ z_out,
                             float* __restrict__ zm_out,
                             float* __restrict__ zl_out) {
    int tid = blockIdx.x * blockDim.x + threadIdx.x;
    if (tid >= BB * LL) return;
    int b = tid >> 5, l = tid & 31;
    const float* h2row = g_h2 + b * HH;
    float am = 0.f, al = 0.f;
    for (int h = 0; h < HH; h++) {
        float hv = __ldg(h2row + h);
        am += hv * zm_w[h * LL + l];
        al += hv * zl_w[h * LL + l];
    }
    am += zm_b[l];
    al += zl_b[l];
    float zv = am + eps[tid] * expf(0.5f * al);
    zm_out[tid] = am;
    zl_out[tid] = al;
    z_out[tid] = zv;
    g_z[tid] = zv;
}

// ---------------------------------------------------------------------------
// TF32 tensor-core fused decoder. One CTA per (column j, 64-batch tile).
//   Zm = W[j] (.) z            [64 x 32]  (tf32 in smem)
//   G1 = relu(Zm @ W1)         [64 x 304] (tf32 in smem, cols 300..303 == 0)
//   x_rec[b] = sum_k relu((G1 @ W2)[b,k] + b2[k]) * col_w[j,k] + col_b[j]
// Warps: w&3 -> M16 stripe, w>>2 -> N half (19 n-tiles each).
// ---------------------------------------------------------------------------
__global__ void __launch_bounds__(256, 1)
decoder_kernel(const float* __restrict__ Wmask,
               const float* __restrict__ gen_w1,
               const float* __restrict__ gen_w2,
               const float* __restrict__ gen_b2,
               const float* __restrict__ col_w,
               const float* __restrict__ col_b,
               float* __restrict__ xmean) {
    extern __shared__ uint32_t sm[];
    uint32_t* Zms = sm;                      // [64][36]
    uint32_t* G1s = Zms + MT * ZS;           // [64][308]
    uint32_t* Wun = G1s + MT * G1S;          // union: W1s[32][312] | W2 dbuf 2x[8][312]
    float*    outs = (float*)(Wun + LL * WS);// [64]

    const int tid  = threadIdx.x;
    const int lane = tid & 31;
    const int warp = tid >> 5;
    const int mrow = (warp & 3) * 16;
    const int nhalf = warp >> 2;
    const int j  = blockIdx.y;
    const int b0 = blockIdx.x * MT;

    // ---- Phase A: stage masked z (tf32) and W1 (tf32, padded) ----
    for (int idx = tid; idx < MT * LL; idx += 256) {
        int bl = idx >> 5, l = idx & 31;
        float v = g_z[(b0 + bl) * LL + l] * Wmask[j * LL + l];
        Zms[bl * ZS + l] = f2tf(v);
    }
    {
        int r0 = tid >> 5, c0 = tid & 31;
        for (int r = r0; r < LL; r += 8)
            for (int c = c0; c < NPAD; c += 32)
                Wun[r * WS + c] = (c < HH) ? f2tf(gen_w1[r * HH + c]) : 0u;
    }
    if (tid < MT) outs[tid] = 0.f;
    __syncthreads();

    float acc[NTW][4];

    // ---- Phase B: G1 = relu(Zm @ W1), K=32 (4 k-steps) ----
    #pragma unroll
    for (int nt = 0; nt < NTW; nt++)
        #pragma unroll
        for (int i = 0; i < 4; i++) acc[nt][i] = 0.f;

    #pragma unroll
    for (int kk = 0; kk < 4; kk++) {
        uint32_t a[4];
        int ar = mrow + (lane >> 2);
        int ac = kk * 8 + (lane & 3);
        a[0] = Zms[ar * ZS + ac];
        a[1] = Zms[(ar + 8) * ZS + ac];
        a[2] = Zms[ar * ZS + ac + 4];
        a[3] = Zms[(ar + 8) * ZS + ac + 4];
        #pragma unroll
        for (int nt = 0; nt < NTW; nt++) {
            int n0 = (nhalf * NTW + nt) * 8;
            uint32_t b[2];
            b[0] = Wun[(kk * 8 + (lane & 3)) * WS + n0 + (lane >> 2)];
            b[1] = Wun[(kk * 8 + (lane & 3) + 4) * WS + n0 + (lane >> 2)];
            mma8(acc[nt], a, b);
        }
    }
    {   // relu + tf32 + store to G1s
        int r = mrow + (lane >> 2);
        #pragma unroll
        for (int nt = 0; nt < NTW; nt++) {
            int c = (nhalf * NTW + nt) * 8 + 2 * (lane & 3);
            G1s[r * G1S + c]           = f2tf(fmaxf(acc[nt][0], 0.f));
            G1s[r * G1S + c + 1]       = f2tf(fmaxf(acc[nt][1], 0.f));
            G1s[(r + 8) * G1S + c]     = f2tf(fmaxf(acc[nt][2], 0.f));
            G1s[(r + 8) * G1S + c + 1] = f2tf(fmaxf(acc[nt][3], 0.f));
        }
    }
    __syncthreads();

    // ---- Phase C: D2 = G1 @ W2, stream W2 in 8-row double-buffered chunks ----
    uint32_t* Wb0 = Wun;
    uint32_t* Wb1 = Wun + 8 * WS;
    {   // prologue: chunk 0
        int r = tid >> 5, c0 = tid & 31;
        for (int c = c0; c < NPAD; c += 32)
            Wb0[r * WS + c] = (c < HH) ? f2tf(gen_w2[r * HH + c]) : 0u;
    }
    #pragma unroll
    for (int nt = 0; nt < NTW; nt++)
        #pragma unroll
        for (int i = 0; i < 4; i++) acc[nt][i] = 0.f;
    __syncthreads();

    for (int kc = 0; kc < KT2; kc++) {
        // register prefetch of chunk kc+1 (overlaps with MMA below)
        float pf[10];
        const int r = tid >> 5, c0 = tid & 31;
        const int h = (kc + 1) * 8 + r;
        const bool havepf = (kc + 1 < KT2);
        if (havepf) {
            #pragma unroll
            for (int i = 0; i < 10; i++) {
                int c = c0 + 32 * i;
                pf[i] = (c < HH && h < HH) ? gen_w2[h * HH + c] : 0.f;
            }
        }

        uint32_t* B = (kc & 1) ? Wb1 : Wb0;
        uint32_t a[4];
        int ar = mrow + (lane >> 2);
        int ac = kc * 8 + (lane & 3);
        a[0] = G1s[ar * G1S + ac];
        a[1] = G1s[(ar + 8) * G1S + ac];
        a[2] = G1s[ar * G1S + ac + 4];
        a[3] = G1s[(ar + 8) * G1S + ac + 4];
        #pragma unroll
        for (int nt = 0; nt < NTW; nt++) {
            int n0 = (nhalf * NTW + nt) * 8;
            uint32_t b[2];
            b[0] = B[(lane & 3) * WS + n0 + (lane >> 2)];
            b[1] = B[((lane & 3) + 4) * WS + n0 + (lane >> 2)];
            mma8(acc[nt], a, b);
        }

        if (havepf) {
            uint32_t* Bn = (kc & 1) ? Wb0 : Wb1;
            #pragma unroll
            for (int i = 0; i < 10; i++) {
                int c = c0 + 32 * i;
                if (c < NPAD) Bn[r * WS + c] = f2tf(pf[i]);
            }
        }
        __syncthreads();
    }

    // ---- Epilogue: relu(D2 + b2) . col_w[j], reduce, write ----
    float rs0 = 0.f, rs1 = 0.f;
    #pragma unroll
    for (int nt = 0; nt < NTW; nt++) {
        int cb = (nhalf * NTW + nt) * 8 + 2 * (lane & 3);
        #pragma unroll
        for (int q = 0; q < 2; q++) {
            int c = cb + q;
            if (c < HH) {
                float bb = gen_b2[c];
                float cw = col_w[j * HH + c];
                rs0 += fmaxf(acc[nt][q] + bb, 0.f) * cw;
                rs1 += fmaxf(acc[nt][2 + q] + bb, 0.f) * cw;
            }
        }
    }
    rs0 += __shfl_xor_sync(0xffffffffu, rs0, 1);
    rs0 += __shfl_xor_sync(0xffffffffu, rs0, 2);
    rs1 += __shfl_xor_sync(0xffffffffu, rs1, 1);
    rs1 += __shfl_xor_sync(0xffffffffu, rs1, 2);
    if ((lane & 3) == 0) {
        int r = mrow + (lane >> 2);
        atomicAdd(&outs[r], rs0);
        atomicAdd(&outs[r + 8], rs1);
    }
    __syncthreads();
    if (tid < MT) {
        xmean[(b0 + tid) * DD + j] = outs[tid] + col_b[j];
    }
}

// ---------------------------------------------------------------------------
// Launch
// ---------------------------------------------------------------------------
extern "C" void kernel_launch(void* const* d_in, const int* in_sizes, int n_in,
                              void* d_out, int out_size) {
    const float* x      = (const float*)d_in[0];
    const float* eps    = (const float*)d_in[1];
    const float* Wmask  = (const float*)d_in[2];
    const float* qz_w1  = (const float*)d_in[3];
    const float* qz_b1  = (const float*)d_in[4];
    const float* qz_w2  = (const float*)d_in[5];
    const float* qz_b2  = (const float*)d_in[6];
    const float* zm_w   = (const float*)d_in[7];
    const float* zm_b   = (const float*)d_in[8];
    const float* zl_w   = (const float*)d_in[9];
    const float* zl_b   = (const float*)d_in[10];
    const float* gen_w1 = (const float*)d_in[11];
    const float* gen_w2 = (const float*)d_in[12];
    const float* gen_b2 = (const float*)d_in[13];
    const float* col_w  = (const float*)d_in[14];
    const float* col_b  = (const float*)d_in[15];

    float* out    = (float*)d_out;
    float* xmean  = out;                       // [B, D]
    float* z_out  = out + BB * DD;             // [B, L]
    float* zm_out = z_out + BB * LL;
    float* zl_out = zm_out + BB * LL;

    float *h1_ptr = nullptr, *h2_ptr = nullptr;
    cudaGetSymbolAddress((void**)&h1_ptr, g_h1);
    cudaGetSymbolAddress((void**)&h2_ptr, g_h2);

    // Encoder GEMM 1: h1 = relu(x @ qz_w1 + qz_b1)
    {
        dim3 grid((HH + 63) / 64, (BB + 63) / 64);
        gemm_bias_relu<<<grid, 256>>>(x, qz_w1, qz_b1, h1_ptr, BB, HH, DD);
    }
    // Encoder GEMM 2: h2 = relu(h1 @ qz_w2 + qz_b2)
    {
        dim3 grid((HH + 63) / 64, (BB + 63) / 64);
        gemm_bias_relu<<<grid, 256>>>(h1_ptr, qz_w2, qz_b2, h2_ptr, BB, HH, HH);
    }
    // Heads
    heads_kernel<<<(BB * LL + 255) / 256, 256>>>(zm_w, zm_b, zl_w, zl_b, eps,
                                                 z_out, zm_out, zl_out);
    // TF32 tensor-core fused decoder
    {
        const int smem_bytes = (MT * ZS + MT * G1S + LL * WS) * 4 + MT * 4;
        cudaFuncSetAttribute(decoder_kernel,
                             cudaFuncAttributeMaxDynamicSharedMemorySize,
                             smem_bytes);
        dim3 grid(BB / MT, DD);
        decoder_kernel<<<grid, 256, smem_bytes>>>(Wmask, gen_w1, gen_w2, gen_b2,
                                                  col_w, col_b, xmean);
    }
}

// round 3
// speedup vs baseline: 8.0583x; 2.3978x over previous
#include <cuda_runtime.h>
#include <cuda_fp16.h>
#include <cuda_bf16.h>
#include <math.h>
#include <stdint.h>

// Problem constants
#define BB 512   // batch
#define DD 512   // input dim / columns
#define LL 32    // latent
#define HH 300   // hidden
#define MT 64    // batch tile (M) in decoder
#define NP 320   // padded N (40 tiles of 8)
#define RS 328   // padded row stride (halves) for W1/W2/G1 smem+gmem
#define KT 19    // k16-chunks in gemm2 (304 = 19*16)
#define ZS 40    // Zms stride in halves
#define CHUNK_H (16 * RS)          // halves per W2 chunk = 5248
#define CHUNK_B (CHUNK_H * 2)      // bytes per chunk = 10496
#define CHUNK_U (CHUNK_B / 16)     // 16B units = 656
#define W1_U    (2 * CHUNK_U)      // W1 = 32 x RS = 1312 units

// ---------------------------------------------------------------------------
// Scratch (device globals: allocation-free rule)
// ---------------------------------------------------------------------------
__device__ float g_h1[BB * HH];
__device__ float g_h2[BB * HH];
__device__ float g_z[BB * LL];
__device__ __half g_w1h[LL * RS];          // [32][328] fp16, padded
__device__ __half g_w2h[KT * CHUNK_H];     // [19][16][328] fp16, chunk-contiguous

// ---------------------------------------------------------------------------
// PTX helpers
// ---------------------------------------------------------------------------
__device__ __forceinline__ void ldsm_x4(uint32_t* r, uint32_t addr) {
    asm volatile("ldmatrix.sync.aligned.m8n8.x4.shared.b16 {%0,%1,%2,%3}, [%4];"
                 : "=r"(r[0]), "=r"(r[1]), "=r"(r[2]), "=r"(r[3]) : "r"(addr));
}
__device__ __forceinline__ void ldsm_x4t(uint32_t* r, uint32_t addr) {
    asm volatile("ldmatrix.sync.aligned.m8n8.x4.trans.shared.b16 {%0,%1,%2,%3}, [%4];"
                 : "=r"(r[0]), "=r"(r[1]), "=r"(r[2]), "=r"(r[3]) : "r"(addr));
}
__device__ __forceinline__ void mma16(float* d, const uint32_t* a, uint32_t b0, uint32_t b1) {
    asm volatile(
        "mma.sync.aligned.m16n8k16.row.col.f32.f16.f16.f32 "
        "{%0,%1,%2,%3}, {%4,%5,%6,%7}, {%8,%9}, {%0,%1,%2,%3};"
        : "+f"(d[0]), "+f"(d[1]), "+f"(d[2]), "+f"(d[3])
        : "r"(a[0]), "r"(a[1]), "r"(a[2]), "r"(a[3]), "r"(b0), "r"(b1));
}
__device__ __forceinline__ void cp16(uint32_t dst, const void* src) {
    asm volatile("cp.async.cg.shared.global [%0], [%1], 16;" :: "r"(dst), "l"(src));
}
__device__ __forceinline__ void cp_commit() {
    asm volatile("cp.async.commit_group;");
}

// ---------------------------------------------------------------------------
// Pack weights to fp16 padded layouts (runs once per launch, tiny)
// ---------------------------------------------------------------------------
__global__ void pack_weights(const float* __restrict__ gen_w1,
                             const float* __restrict__ gen_w2) {
    int idx = blockIdx.x * blockDim.x + threadIdx.x;
    if (idx < LL * RS) {
        int r = idx / RS, c = idx % RS;
        g_w1h[idx] = (c < HH) ? __float2half(gen_w1[r * HH + c]) : __half(0.f);
    } else {
        int i2 = idx - LL * RS;
        if (i2 < KT * CHUNK_H) {
            int k = i2 / RS, c = i2 % RS;   // k = chunk*16 + row
            g_w2h[i2] = (k < HH && c < HH) ? __float2half(gen_w2[k * HH + c])
                                           : __half(0.f);
        }
    }
}

// ---------------------------------------------------------------------------
// Generic tiled SGEMM with bias + relu (encoder)
// ---------------------------------------------------------------------------
__global__ void gemm_bias_relu(const float* __restrict__ A,
                               const float* __restrict__ Bw,
                               const float* __restrict__ bias,
                               float* __restrict__ C,
                               int M, int N, int K) {
    const int BK = 8;
    __shared__ float As[BK][64];
    __shared__ float Bs[BK][64];
    int tid = threadIdx.x;
    int tx = tid % 16, ty = tid / 16;
    int rowBase = blockIdx.y * 64;
    int colBase = blockIdx.x * 64;
    float acc[4][4] = {};
    for (int k0 = 0; k0 < K; k0 += BK) {
        #pragma unroll
        for (int i = 0; i < 2; i++) {
            int idx = tid * 2 + i;
            int r = idx / BK, kk = idx % BK;
            int gr = rowBase + r, gk = k0 + kk;
            As[kk][r] = (gr < M && gk < K) ? A[gr * K + gk] : 0.f;
        }
        #pragma unroll
        for (int i = 0; i < 2; i++) {
            int idx = tid * 2 + i;
            int kk = idx / 64, c = idx % 64;
            int gc = colBase + c, gk = k0 + kk;
            Bs[kk][c] = (gc < N && gk < K) ? Bw[gk * N + gc] : 0.f;
        }
        __syncthreads();
        #pragma unroll
        for (int kk = 0; kk < BK; kk++) {
            float a[4], b[4];
            #pragma unroll
            for (int i = 0; i < 4; i++) a[i] = As[kk][ty * 4 + i];
            #pragma unroll
            for (int jj = 0; jj < 4; jj++) b[jj] = Bs[kk][tx * 4 + jj];
            #pragma unroll
            for (int i = 0; i < 4; i++)
                #pragma unroll
                for (int jj = 0; jj < 4; jj++)
                    acc[i][jj] += a[i] * b[jj];
        }
        __syncthreads();
    }
    #pragma unroll
    for (int i = 0; i < 4; i++) {
        int r = rowBase + ty * 4 + i;
        if (r >= M) continue;
        #pragma unroll
        for (int jj = 0; jj < 4; jj++) {
            int c = colBase + tx * 4 + jj;
            if (c >= N) continue;
            float v = acc[i][jj] + bias[c];
            C[r * N + c] = v > 0.f ? v : 0.f;
        }
    }
}

// ---------------------------------------------------------------------------
// Heads: z_mean, z_log_var, z from h2. One thread per (b, l).
// ---------------------------------------------------------------------------
__global__ void heads_kernel(const float* __restrict__ zm_w,
                             const float* __restrict__ zm_b,
                             const float* __restrict__ zl_w,
                             const float* __restrict__ zl_b,
                             const float* __restrict__ eps,
                             float* __restrict__ z_out,
                             float* __restrict__ zm_out,
                             float* __restrict__ zl_out) {
    int tid = blockIdx.x * blockDim.x + threadIdx.x;
    if (tid >= BB * LL) return;
    int b = tid >> 5, l = tid & 31;
    const float* h2row = g_h2 + b * HH;
    float am = 0.f, al = 0.f;
    for (int h = 0; h < HH; h++) {
        float hv = __ldg(h2row + h);
        am += hv * zm_w[h * LL + l];
        al += hv * zl_w[h * LL + l];
    }
    am += zm_b[l];
    al += zl_b[l];
    float zv = am + eps[tid] * expf(0.5f * al);
    zm_out[tid] = am;
    zl_out[tid] = al;
    z_out[tid] = zv;
    g_z[tid] = zv;
}

// ---------------------------------------------------------------------------
// fp16 tensor-core fused decoder. One CTA per (column j, 64-batch tile).
// 512 threads = 16 warps = 4 m-stripes x 4 n-quarters (10 n8-tiles each).
// SMEM (halves): Zms[64][40] | G1s[64][328] | ring[4][16*328] | outs(f32)[64]
// W1 occupies ring stages 0-1 during gemm1.
// ---------------------------------------------------------------------------
__global__ void __launch_bounds__(512, 1)
decoder_kernel(const float* __restrict__ Wmask,
               const float* __restrict__ gen_b2,
               const float* __restrict__ col_w,
               const float* __restrict__ col_b,
               float* __restrict__ xmean) {
    extern __shared__ __half sh[];
    __half* Zms  = sh;                     // 2560 halves
    __half* G1s  = sh + MT * ZS;           // 20992 halves
    __half* ring = G1s + MT * RS;          // 4*5248 halves
    float*  outs = (float*)(ring + 4 * CHUNK_H);

    const int tid  = threadIdx.x;
    const int lane = tid & 31;
    const int warp = tid >> 5;
    const int r0   = (warp & 3) * 16;      // m-stripe
    const int nq   = warp >> 2;            // n-quarter (0..3)
    const int j    = blockIdx.y;
    const int b0   = blockIdx.x * MT;
    const int seg  = lane >> 3, rr = lane & 7;

    const uint32_t zms_a  = (uint32_t)__cvta_generic_to_shared(Zms);
    const uint32_t g1s_a  = (uint32_t)__cvta_generic_to_shared(G1s);
    const uint32_t ring_a = (uint32_t)__cvta_generic_to_shared(ring);

    // ---- prologue cp.async: W1 (stages 0-1), chunk0 (stage2), chunk1 (stage3)
    {
        const __half* w1 = g_w1h;
        for (int u = tid; u < W1_U; u += 512)
            cp16(ring_a + u * 16, w1 + u * 8);
        cp_commit();                                        // group: W1
        const __half* c0 = g_w2h;
        for (int u = tid; u < CHUNK_U; u += 512)
            cp16(ring_a + 2 * CHUNK_B + u * 16, c0 + u * 8);
        cp_commit();                                        // group: c0
        const __half* c1 = g_w2h + CHUNK_H;
        for (int u = tid; u < CHUNK_U; u += 512)
            cp16(ring_a + 3 * CHUNK_B + u * 16, c1 + u * 8);
        cp_commit();                                        // group: c1
    }

    // ---- stage masked z as fp16
    for (int idx = tid; idx < MT * LL; idx += 512) {
        int bl = idx >> 5, l = idx & 31;
        float v = g_z[(b0 + bl) * LL + l] * __ldg(Wmask + j * LL + l);
        Zms[bl * ZS + l] = __float2half(v);
    }
    if (tid < MT) outs[tid] = 0.f;

    asm volatile("cp.async.wait_group 2;");                 // W1 ready
    __syncthreads();

    // per-lane ldmatrix address components
    // A (row-major 16x16): row = r0 + (seg&1)*8 + rr, colbase = (seg>>1)*8
    const int a_row = r0 + (seg & 1) * 8 + rr;
    const int a_cb  = (seg >> 1) * 8;
    // B (k x n row-major, trans): k = (seg&1)*8 + rr, nb = (seg>>1)*8
    const int b_k  = (seg & 1) * 8 + rr;
    const int b_nb = (seg >> 1) * 8;

    float acc[10][4];
    #pragma unroll
    for (int t = 0; t < 10; t++)
        #pragma unroll
        for (int i = 0; i < 4; i++) acc[t][i] = 0.f;

    // ---- gemm1: G1 = relu(Zm @ W1), K=32 (2 k16 steps), W1 in ring[0..1]
    #pragma unroll
    for (int kk = 0; kk < 2; kk++) {
        uint32_t a[4];
        ldsm_x4(a, zms_a + (a_row * ZS + kk * 16 + a_cb) * 2);
        #pragma unroll
        for (int p = 0; p < 5; p++) {
            int n0 = (nq * 10 + 2 * p) * 8;
            uint32_t b[4];
            ldsm_x4t(b, ring_a + ((kk * 16 + b_k) * RS + n0 + b_nb) * 2);
            mma16(acc[2 * p],     a, b[0], b[1]);
            mma16(acc[2 * p + 1], a, b[2], b[3]);
        }
    }
    {   // relu + pack -> G1s
        int row = r0 + (lane >> 2);
        #pragma unroll
        for (int t = 0; t < 10; t++) {
            int c = (nq * 10 + t) * 8 + 2 * (lane & 3);
            __half2 lo = __floats2half2_rn(fmaxf(acc[t][0], 0.f), fmaxf(acc[t][1], 0.f));
            __half2 hi = __floats2half2_rn(fmaxf(acc[t][2], 0.f), fmaxf(acc[t][3], 0.f));
            *(__half2*)(G1s + row * RS + c)       = lo;
            *(__half2*)(G1s + (row + 8) * RS + c) = hi;
            acc[t][0] = acc[t][1] = acc[t][2] = acc[t][3] = 0.f;
        }
    }
    __syncthreads();    // G1s visible; ring stages 0,1 free

    // issue chunk2 -> stage0
    {
        const __half* c2 = g_w2h + 2 * CHUNK_H;
        for (int u = tid; u < CHUNK_U; u += 512)
            cp16(ring_a + 0 * CHUNK_B + u * 16, c2 + u * 8);
        cp_commit();                                        // group: c2
    }

    // ---- gemm2 mainloop: 19 chunks, stage(kc) = (kc+2)&3
    for (int kc = 0; kc < KT; kc++) {
        asm volatile("cp.async.wait_group 2;");
        __syncthreads();

        // issue chunk kc+3 into stage (kc+1)&3 (freed last iteration)
        if (kc + 3 < KT) {
            const __half* src = g_w2h + (kc + 3) * CHUNK_H;
            uint32_t dst = ring_a + ((kc + 1) & 3) * CHUNK_B;
            for (int u = tid; u < CHUNK_U; u += 512)
                cp16(dst + u * 16, src + u * 8);
        }
        cp_commit();    // one group per iteration (possibly empty)

        const uint32_t Bs = ring_a + ((kc + 2) & 3) * CHUNK_B;
        uint32_t a[4];
        ldsm_x4(a, g1s_a + (a_row * RS + kc * 16 + a_cb) * 2);
        #pragma unroll
        for (int p = 0; p < 5; p++) {
            int n0 = (nq * 10 + 2 * p) * 8;
            uint32_t b[4];
            ldsm_x4t(b, Bs + (b_k * RS + n0 + b_nb) * 2);
            mma16(acc[2 * p],     a, b[0], b[1]);
            mma16(acc[2 * p + 1], a, b[2], b[3]);
        }
    }

    // ---- epilogue: relu(D2 + b2) . col_w[j], reduce
    float rs0 = 0.f, rs1 = 0.f;
    #pragma unroll
    for (int t = 0; t < 10; t++) {
        int cb = (nq * 10 + t) * 8 + 2 * (lane & 3);
        #pragma unroll
        for (int q = 0; q < 2; q++) {
            int c = cb + q;
            if (c < HH) {
                float bb = __ldg(gen_b2 + c);
                float cw = __ldg(col_w + j * HH + c);
                rs0 += fmaxf(acc[t][q] + bb, 0.f) * cw;
                rs1 += fmaxf(acc[t][2 + q] + bb, 0.f) * cw;
            }
        }
    }
    rs0 += __shfl_xor_sync(0xffffffffu, rs0, 1);
    rs0 += __shfl_xor_sync(0xffffffffu, rs0, 2);
    rs1 += __shfl_xor_sync(0xffffffffu, rs1, 1);
    rs1 += __shfl_xor_sync(0xffffffffu, rs1, 2);
    if ((lane & 3) == 0) {
        atomicAdd(&outs[r0 + (lane >> 2)], rs0);
        atomicAdd(&outs[r0 + 8 + (lane >> 2)], rs1);
    }
    __syncthreads();
    if (tid < MT) {
        xmean[(b0 + tid) * DD + j] = outs[tid] + __ldg(col_b + j);
    }
}

// ---------------------------------------------------------------------------
// Launch
// ---------------------------------------------------------------------------
extern "C" void kernel_launch(void* const* d_in, const int* in_sizes, int n_in,
                              void* d_out, int out_size) {
    const float* x      = (const float*)d_in[0];
    const float* eps    = (const float*)d_in[1];
    const float* Wmask  = (const float*)d_in[2];
    const float* qz_w1  = (const float*)d_in[3];
    const float* qz_b1  = (const float*)d_in[4];
    const float* qz_w2  = (const float*)d_in[5];
    const float* qz_b2  = (const float*)d_in[6];
    const float* zm_w   = (const float*)d_in[7];
    const float* zm_b   = (const float*)d_in[8];
    const float* zl_w   = (const float*)d_in[9];
    const float* zl_b   = (const float*)d_in[10];
    const float* gen_w1 = (const float*)d_in[11];
    const float* gen_w2 = (const float*)d_in[12];
    const float* gen_b2 = (const float*)d_in[13];
    const float* col_w  = (const float*)d_in[14];
    const float* col_b  = (const float*)d_in[15];

    float* out    = (float*)d_out;
    float* xmean  = out;                       // [B, D]
    float* z_out  = out + BB * DD;             // [B, L]
    float* zm_out = z_out + BB * LL;
    float* zl_out = zm_out + BB * LL;

    float *h1_ptr = nullptr, *h2_ptr = nullptr;
    cudaGetSymbolAddress((void**)&h1_ptr, g_h1);
    cudaGetSymbolAddress((void**)&h2_ptr, g_h2);

    // Pack weights to fp16 (overlaps nothing, but tiny)
    {
        int total = LL * RS + KT * CHUNK_H;
        pack_weights<<<(total + 255) / 256, 256>>>(gen_w1, gen_w2);
    }
    // Encoder
    {
        dim3 grid((HH + 63) / 64, (BB + 63) / 64);
        gemm_bias_relu<<<grid, 256>>>(x, qz_w1, qz_b1, h1_ptr, BB, HH, DD);
        gemm_bias_relu<<<grid, 256>>>(h1_ptr, qz_w2, qz_b2, h2_ptr, BB, HH, HH);
    }
    heads_kernel<<<(BB * LL + 255) / 256, 256>>>(zm_w, zm_b, zl_w, zl_b, eps,
                                                 z_out, zm_out, zl_out);
    // fp16 tensor-core fused decoder
    {
        const int smem_bytes = (MT * ZS + MT * RS + 4 * CHUNK_H) * 2 + MT * 4;
        cudaFuncSetAttribute(decoder_kernel,
                             cudaFuncAttributeMaxDynamicSharedMemorySize,
                             smem_bytes);
        dim3 grid(BB / MT, DD);
        decoder_kernel<<<grid, 512, smem_bytes>>>(Wmask, gen_b2, col_w, col_b,
                                                  xmean);
    }
}

// round 5
// speedup vs baseline: 9.5449x; 1.1845x over previous
#include <cuda_runtime.h>
#include <cuda_fp16.h>
#include <cuda_bf16.h>
#include <math.h>
#include <stdint.h>

// Problem constants
#define BB 512   // batch
#define DD 512   // input dim / columns
#define LL 32    // latent
#define HH 300   // hidden
#define MT 128   // batch tile (M) in decoder
#define NP 320   // padded N (40 tiles of 8)
#define RS 328   // padded row stride (halves) for W1/W2/G1 smem+gmem
#define KT 19    // k16-chunks in gemm2 (304 = 19*16)
#define ZS 40    // Zms stride in halves
#define CHUNK_H (16 * RS)          // halves per W2 chunk = 5248
#define CHUNK_B (CHUNK_H * 2)      // bytes per chunk = 10496
#define CHUNK_U (CHUNK_B / 16)     // 16B units = 656
#define W1_U    (2 * CHUNK_U)      // W1 = 32 x RS = 1312 units

// ---------------------------------------------------------------------------
// Scratch (device globals: allocation-free rule)
// ---------------------------------------------------------------------------
__device__ float g_h1[BB * HH];
__device__ float g_h2[BB * HH];
__device__ float g_z[BB * LL];
__device__ __half g_w1h[LL * RS];          // [32][328] fp16, padded
__device__ __half g_w2h[KT * CHUNK_H];     // [19][16][328] fp16, chunk-contiguous

// ---------------------------------------------------------------------------
// PTX helpers
// ---------------------------------------------------------------------------
__device__ __forceinline__ void ldsm_x4(uint32_t* r, uint32_t addr) {
    asm volatile("ldmatrix.sync.aligned.m8n8.x4.shared.b16 {%0,%1,%2,%3}, [%4];"
                 : "=r"(r[0]), "=r"(r[1]), "=r"(r[2]), "=r"(r[3]) : "r"(addr));
}
__device__ __forceinline__ void ldsm_x4t(uint32_t* r, uint32_t addr) {
    asm volatile("ldmatrix.sync.aligned.m8n8.x4.trans.shared.b16 {%0,%1,%2,%3}, [%4];"
                 : "=r"(r[0]), "=r"(r[1]), "=r"(r[2]), "=r"(r[3]) : "r"(addr));
}
__device__ __forceinline__ void mma16(float* d, const uint32_t* a, uint32_t b0, uint32_t b1) {
    asm volatile(
        "mma.sync.aligned.m16n8k16.row.col.f32.f16.f16.f32 "
        "{%0,%1,%2,%3}, {%4,%5,%6,%7}, {%8,%9}, {%0,%1,%2,%3};"
        : "+f"(d[0]), "+f"(d[1]), "+f"(d[2]), "+f"(d[3])
        : "r"(a[0]), "r"(a[1]), "r"(a[2]), "r"(a[3]), "r"(b0), "r"(b1));
}
__device__ __forceinline__ void cp16(uint32_t dst, const void* src) {
    asm volatile("cp.async.cg.shared.global [%0], [%1], 16;" :: "r"(dst), "l"(src));
}
__device__ __forceinline__ void cp_commit() {
    asm volatile("cp.async.commit_group;");
}

// ---------------------------------------------------------------------------
// Pack weights to fp16 padded layouts
// ---------------------------------------------------------------------------
__global__ void pack_weights(const float* __restrict__ gen_w1,
                             const float* __restrict__ gen_w2) {
    int idx = blockIdx.x * blockDim.x + threadIdx.x;
    if (idx < LL * RS) {
        int r = idx / RS, c = idx % RS;
        g_w1h[idx] = (c < HH) ? __float2half(gen_w1[r * HH + c]) : __half(0.f);
    } else {
        int i2 = idx - LL * RS;
        if (i2 < KT * CHUNK_H) {
            int k = i2 / RS, c = i2 % RS;
            g_w2h[i2] = (k < HH && c < HH) ? __float2half(gen_w2[k * HH + c])
                                           : __half(0.f);
        }
    }
}

// ---------------------------------------------------------------------------
// Generic tiled SGEMM with bias + relu (encoder)
// ---------------------------------------------------------------------------
__global__ void gemm_bias_relu(const float* __restrict__ A,
                               const float* __restrict__ Bw,
                               const float* __restrict__ bias,
                               float* __restrict__ C,
                               int M, int N, int K) {
    const int BK = 8;
    __shared__ float As[BK][64];
    __shared__ float Bs[BK][64];
    int tid = threadIdx.x;
    int tx = tid % 16, ty = tid / 16;
    int rowBase = blockIdx.y * 64;
    int colBase = blockIdx.x * 64;
    float acc[4][4] = {};
    for (int k0 = 0; k0 < K; k0 += BK) {
        #pragma unroll
        for (int i = 0; i < 2; i++) {
            int idx = tid * 2 + i;
            int r = idx / BK, kk = idx % BK;
            int gr = rowBase + r, gk = k0 + kk;
            As[kk][r] = (gr < M && gk < K) ? A[gr * K + gk] : 0.f;
        }
        #pragma unroll
        for (int i = 0; i < 2; i++) {
            int idx = tid * 2 + i;
            int kk = idx / 64, c = idx % 64;
            int gc = colBase + c, gk = k0 + kk;
            Bs[kk][c] = (gc < N && gk < K) ? Bw[gk * N + gc] : 0.f;
        }
        __syncthreads();
        #pragma unroll
        for (int kk = 0; kk < BK; kk++) {
            float a[4], b[4];
            #pragma unroll
            for (int i = 0; i < 4; i++) a[i] = As[kk][ty * 4 + i];
            #pragma unroll
            for (int jj = 0; jj < 4; jj++) b[jj] = Bs[kk][tx * 4 + jj];
            #pragma unroll
            for (int i = 0; i < 4; i++)
                #pragma unroll
                for (int jj = 0; jj < 4; jj++)
                    acc[i][jj] += a[i] * b[jj];
        }
        __syncthreads();
    }
    #pragma unroll
    for (int i = 0; i < 4; i++) {
        int r = rowBase + ty * 4 + i;
        if (r >= M) continue;
        #pragma unroll
        for (int jj = 0; jj < 4; jj++) {
            int c = colBase + tx * 4 + jj;
            if (c >= N) continue;
            float v = acc[i][jj] + bias[c];
            C[r * N + c] = v > 0.f ? v : 0.f;
        }
    }
}

// ---------------------------------------------------------------------------
// Heads: unroll-4, 8 independent accumulators -> MLP 8, short dep chains
// ---------------------------------------------------------------------------
__global__ void heads_kernel(const float* __restrict__ zm_w,
                             const float* __restrict__ zm_b,
                             const float* __restrict__ zl_w,
                             const float* __restrict__ zl_b,
                             const float* __restrict__ eps,
                             float* __restrict__ z_out,
                             float* __restrict__ zm_out,
                             float* __restrict__ zl_out) {
    int tid = blockIdx.x * blockDim.x + threadIdx.x;
    if (tid >= BB * LL) return;
    int b = tid >> 5, l = tid & 31;
    const float* h2row = g_h2 + b * HH;
    float am0 = 0.f, am1 = 0.f, am2 = 0.f, am3 = 0.f;
    float al0 = 0.f, al1 = 0.f, al2 = 0.f, al3 = 0.f;
    #pragma unroll 2
    for (int h = 0; h < HH; h += 4) {
        float hv0 = __ldg(h2row + h);
        float hv1 = __ldg(h2row + h + 1);
        float hv2 = __ldg(h2row + h + 2);
        float hv3 = __ldg(h2row + h + 3);
        am0 += hv0 * __ldg(zm_w + (h    ) * LL + l);
        am1 += hv1 * __ldg(zm_w + (h + 1) * LL + l);
        am2 += hv2 * __ldg(zm_w + (h + 2) * LL + l);
        am3 += hv3 * __ldg(zm_w + (h + 3) * LL + l);
        al0 += hv0 * __ldg(zl_w + (h    ) * LL + l);
        al1 += hv1 * __ldg(zl_w + (h + 1) * LL + l);
        al2 += hv2 * __ldg(zl_w + (h + 2) * LL + l);
        al3 += hv3 * __ldg(zl_w + (h + 3) * LL + l);
    }
    float am = ((am0 + am1) + (am2 + am3)) + zm_b[l];
    float al = ((al0 + al1) + (al2 + al3)) + zl_b[l];
    float zv = am + eps[tid] * expf(0.5f * al);
    zm_out[tid] = am;
    zl_out[tid] = al;
    z_out[tid] = zv;
    g_z[tid] = zv;
}

// ---------------------------------------------------------------------------
// fp16 tensor-core fused decoder. One CTA per (column j, 128-batch tile).
// 512 threads = 16 warps: warp & 3 -> m 32-row stripe (2 m16 tiles),
//                         warp >> 2 -> n-quarter (10 n8-tiles).
// SMEM (halves): Zms[128][40] | G1s[128][328] | ring[4][16*328] | outs(f32)[128]
// ---------------------------------------------------------------------------
__global__ void __launch_bounds__(512, 1)
decoder_kernel(const float* __restrict__ Wmask,
               const float* __restrict__ gen_b2,
               const float* __restrict__ col_w,
               const float* __restrict__ col_b,
               float* __restrict__ xmean) {
    extern __shared__ __half sh[];
    __half* Zms  = sh;                     // 5120 halves
    __half* G1s  = sh + MT * ZS;           // 41984 halves
    __half* ring = G1s + MT * RS;          // 4*5248 halves
    float*  outs = (float*)(ring + 4 * CHUNK_H);

    const int tid  = threadIdx.x;
    const int lane = tid & 31;
    const int warp = tid >> 5;
    const int r0   = (warp & 3) * 32;      // m-stripe (2 m16 tiles)
    const int nq   = warp >> 2;            // n-quarter (0..3)
    const int j    = blockIdx.y;
    const int b0   = blockIdx.x * MT;
    const int seg  = lane >> 3, rr = lane & 7;

    const uint32_t zms_a  = (uint32_t)__cvta_generic_to_shared(Zms);
    const uint32_t g1s_a  = (uint32_t)__cvta_generic_to_shared(G1s);
    const uint32_t ring_a = (uint32_t)__cvta_generic_to_shared(ring);

    // ---- prologue cp.async: W1 (stages 0-1), chunk0 (stage2), chunk1 (stage3)
    {
        const __half* w1 = g_w1h;
        for (int u = tid; u < W1_U; u += 512)
            cp16(ring_a + u * 16, w1 + u * 8);
        cp_commit();                                        // group: W1
        const __half* c0 = g_w2h;
        for (int u = tid; u < CHUNK_U; u += 512)
            cp16(ring_a + 2 * CHUNK_B + u * 16, c0 + u * 8);
        cp_commit();                                        // group: c0
        const __half* c1 = g_w2h + CHUNK_H;
        for (int u = tid; u < CHUNK_U; u += 512)
            cp16(ring_a + 3 * CHUNK_B + u * 16, c1 + u * 8);
        cp_commit();                                        // group: c1
    }

    // ---- stage masked z as fp16
    for (int idx = tid; idx < MT * LL; idx += 512) {
        int bl = idx >> 5, l = idx & 31;
        float v = g_z[(b0 + bl) * LL + l] * __ldg(Wmask + j * LL + l);
        Zms[bl * ZS + l] = __float2half(v);
    }
    if (tid < MT) outs[tid] = 0.f;

    asm volatile("cp.async.wait_group 2;");                 // W1 ready
    __syncthreads();

    // ldmatrix lane address components
    const int a_ro = (seg & 1) * 8 + rr;   // row offset within m16 tile
    const int a_cb = (seg >> 1) * 8;       // col base within k16
    const int b_k  = (seg & 1) * 8 + rr;   // k within chunk
    const int b_nb = (seg >> 1) * 8;       // n offset within n16 pair

    float acc[2][10][4];
    #pragma unroll
    for (int m = 0; m < 2; m++)
        #pragma unroll
        for (int t = 0; t < 10; t++)
            #pragma unroll
            for (int i = 0; i < 4; i++) acc[m][t][i] = 0.f;

    // ---- gemm1: G1 = relu(Zm @ W1), K=32 (2 k16 steps), W1 in ring[0..1]
    #pragma unroll
    for (int kk = 0; kk < 2; kk++) {
        uint32_t a[2][4];
        #pragma unroll
        for (int m = 0; m < 2; m++)
            ldsm_x4(a[m], zms_a + ((r0 + m * 16 + a_ro) * ZS + kk * 16 + a_cb) * 2);
        #pragma unroll
        for (int p = 0; p < 5; p++) {
            int n0 = (nq * 10 + 2 * p) * 8;
            uint32_t b[4];
            ldsm_x4t(b, ring_a + ((kk * 16 + b_k) * RS + n0 + b_nb) * 2);
            #pragma unroll
            for (int m = 0; m < 2; m++) {
                mma16(acc[m][2 * p],     a[m], b[0], b[1]);
                mma16(acc[m][2 * p + 1], a[m], b[2], b[3]);
            }
        }
    }
    {   // relu + pack -> G1s
        #pragma unroll
        for (int m = 0; m < 2; m++) {
            int row = r0 + m * 16 + (lane >> 2);
            #pragma unroll
            for (int t = 0; t < 10; t++) {
                int c = (nq * 10 + t) * 8 + 2 * (lane & 3);
                __half2 lo = __floats2half2_rn(fmaxf(acc[m][t][0], 0.f), fmaxf(acc[m][t][1], 0.f));
                __half2 hi = __floats2half2_rn(fmaxf(acc[m][t][2], 0.f), fmaxf(acc[m][t][3], 0.f));
                *(__half2*)(G1s + row * RS + c)       = lo;
                *(__half2*)(G1s + (row + 8) * RS + c) = hi;
                acc[m][t][0] = acc[m][t][1] = acc[m][t][2] = acc[m][t][3] = 0.f;
            }
        }
    }
    __syncthreads();    // G1s visible; ring stages 0,1 free

    // issue chunk2 -> stage0
    {
        const __half* c2 = g_w2h + 2 * CHUNK_H;
        for (int u = tid; u < CHUNK_U; u += 512)
            cp16(ring_a + 0 * CHUNK_B + u * 16, c2 + u * 8);
        cp_commit();                                        // group: c2
    }

    // ---- gemm2 mainloop: 19 chunks, stage(kc) = (kc+2)&3
    for (int kc = 0; kc < KT; kc++) {
        asm volatile("cp.async.wait_group 2;");
        __syncthreads();

        if (kc + 3 < KT) {
            const __half* src = g_w2h + (kc + 3) * CHUNK_H;
            uint32_t dst = ring_a + ((kc + 1) & 3) * CHUNK_B;
            for (int u = tid; u < CHUNK_U; u += 512)
                cp16(dst + u * 16, src + u * 8);
        }
        cp_commit();    // one group per iteration (possibly empty)

        const uint32_t Bs = ring_a + ((kc + 2) & 3) * CHUNK_B;
        uint32_t a[2][4];
        #pragma unroll
        for (int m = 0; m < 2; m++)
            ldsm_x4(a[m], g1s_a + ((r0 + m * 16 + a_ro) * RS + kc * 16 + a_cb) * 2);
        #pragma unroll
        for (int p = 0; p < 5; p++) {
            int n0 = (nq * 10 + 2 * p) * 8;
            uint32_t b[4];
            ldsm_x4t(b, Bs + (b_k * RS + n0 + b_nb) * 2);
            #pragma unroll
            for (int m = 0; m < 2; m++) {
                mma16(acc[m][2 * p],     a[m], b[0], b[1]);
                mma16(acc[m][2 * p + 1], a[m], b[2], b[3]);
            }
        }
    }

    // ---- epilogue: relu(D2 + b2) . col_w[j], reduce
    #pragma unroll
    for (int m = 0; m < 2; m++) {
        float rs0 = 0.f, rs1 = 0.f;
        #pragma unroll
        for (int t = 0; t < 10; t++) {
            int cb = (nq * 10 + t) * 8 + 2 * (lane & 3);
            #pragma unroll
            for (int q = 0; q < 2; q++) {
                int c = cb + q;
                if (c < HH) {
                    float bb = __ldg(gen_b2 + c);
                    float cw = __ldg(col_w + j * HH + c);
                    rs0 += fmaxf(acc[m][t][q] + bb, 0.f) * cw;
                    rs1 += fmaxf(acc[m][t][2 + q] + bb, 0.f) * cw;
                }
            }
        }
        rs0 += __shfl_xor_sync(0xffffffffu, rs0, 1);
        rs0 += __shfl_xor_sync(0xffffffffu, rs0, 2);
        rs1 += __shfl_xor_sync(0xffffffffu, rs1, 1);
        rs1 += __shfl_xor_sync(0xffffffffu, rs1, 2);
        if ((lane & 3) == 0) {
            int rbase = r0 + m * 16 + (lane >> 2);
            atomicAdd(&outs[rbase], rs0);
            atomicAdd(&outs[rbase + 8], rs1);
        }
    }
    __syncthreads();
    if (tid < MT) {
        xmean[(b0 + tid) * DD + j] = outs[tid] + __ldg(col_b + j);
    }
}

// ---------------------------------------------------------------------------
// Launch
// ---------------------------------------------------------------------------
extern "C" void kernel_launch(void* const* d_in, const int* in_sizes, int n_in,
                              void* d_out, int out_size) {
    const float* x      = (const float*)d_in[0];
    const float* eps    = (const float*)d_in[1];
    const float* Wmask  = (const float*)d_in[2];
    const float* qz_w1  = (const float*)d_in[3];
    const float* qz_b1  = (const float*)d_in[4];
    const float* qz_w2  = (const float*)d_in[5];
    const float* qz_b2  = (const float*)d_in[6];
    const float* zm_w   = (const float*)d_in[7];
    const float* zm_b   = (const float*)d_in[8];
    const float* zl_w   = (const float*)d_in[9];
    const float* zl_b   = (const float*)d_in[10];
    const float* gen_w1 = (const float*)d_in[11];
    const float* gen_w2 = (const float*)d_in[12];
    const float* gen_b2 = (const float*)d_in[13];
    const float* col_w  = (const float*)d_in[14];
    const float* col_b  = (const float*)d_in[15];

    float* out    = (float*)d_out;
    float* xmean  = out;                       // [B, D]
    float* z_out  = out + BB * DD;             // [B, L]
    float* zm_out = z_out + BB * LL;
    float* zl_out = zm_out + BB * LL;

    float *h1_ptr = nullptr, *h2_ptr = nullptr;
    cudaGetSymbolAddress((void**)&h1_ptr, g_h1);
    cudaGetSymbolAddress((void**)&h2_ptr, g_h2);

    // Pack weights to fp16
    {
        int total = LL * RS + KT * CHUNK_H;
        pack_weights<<<(total + 255) / 256, 256>>>(gen_w1, gen_w2);
    }
    // Encoder
    {
        dim3 grid((HH + 63) / 64, (BB + 63) / 64);
        gemm_bias_relu<<<grid, 256>>>(x, qz_w1, qz_b1, h1_ptr, BB, HH, DD);
        gemm_bias_relu<<<grid, 256>>>(h1_ptr, qz_w2, qz_b2, h2_ptr, BB, HH, HH);
    }
    heads_kernel<<<(BB * LL + 255) / 256, 256>>>(zm_w, zm_b, zl_w, zl_b, eps,
                                                 z_out, zm_out, zl_out);
    // fp16 tensor-core fused decoder
    {
        const int smem_bytes = (MT * ZS + MT * RS + 4 * CHUNK_H) * 2 + MT * 4;
        cudaFuncSetAttribute(decoder_kernel,
                             cudaFuncAttributeMaxDynamicSharedMemorySize,
                             smem_bytes);
        dim3 grid(BB / MT, DD);
        decoder_kernel<<<grid, 512, smem_bytes>>>(Wmask, gen_b2, col_w, col_b,
                                                  xmean);
    }
}